// round 17
// baseline (speedup 1.0000x reference)
#include <cuda_runtime.h>
#include <cstdint>

#define NX 128
#define NU 64
#define ND 192
#define TH 2048
#define GB 32
#define NT 256
#define RPB 6
#define SEG 32
#define IT_SW 20
#define PB 17

// dynamic smem layout (float offsets) -- no aliasing
#define OFF_FU   0        // 128x64  F_u, staged once
#define OFF_QXU  8192     // 128x64
#define OFF_QUU  16384    // 64x64
#define OFF_X    20480    // 64x64 row-major
#define OFF_XT   24576    // 64x64 transposed
#define OFF_Y4   28672    // 4x64
#define OFF_QU   28928    // 64
#define SMEM_FLOATS 28992
#define SMEM_BK (SMEM_FLOATS * 4)

__device__ __align__(16) float g_Ft[ND * NX];
__device__ __align__(16) float g_Vb[2][NX * NX];
__device__ __align__(16) float g_vb[2][NX];
__device__ __align__(16) float g_Q[ND * ND];
__device__ __align__(16) float g_q[ND];
__device__ __align__(16) float g_invb[2][NU * NU];
__device__ __align__(16) float g_invbT[2][NU * NU];
__device__ __align__(16) float g_Ks[(size_t)TH * NU * NX];
__device__ __align__(16) float g_ks[TH * NU];
__device__ __align__(16) float g_Ms[(size_t)TH * NX * NX];
__device__ __align__(16) float g_bs[TH * NX];
__device__ __align__(16) float g_P[2][NX * NX];
__device__ __align__(16) float g_pb[2][NX];
__device__ unsigned g_delta[TH];
__device__ unsigned g_vmax[TH];
__device__ int g_niters;
__device__ unsigned g_barcnt = 0;
__device__ unsigned g_bargen = 0;
__device__ unsigned g_barcnt2 = 0;
__device__ unsigned g_bargen2 = 0;

// acquire/release grid barrier: no full membar, L2-latency poll only
__device__ __forceinline__ void gbar_n(unsigned* cnt, unsigned* gen_p, unsigned nb) {
    __syncthreads();
    if (threadIdx.x == 0) {
        unsigned gen;
        asm volatile("ld.acquire.gpu.global.u32 %0, [%1];" : "=r"(gen) : "l"(gen_p) : "memory");
        unsigned arrived;
        asm volatile("atom.acq_rel.gpu.global.add.u32 %0, [%1], 1;" : "=r"(arrived) : "l"(cnt) : "memory");
        if (arrived == nb - 1) {
            asm volatile("st.relaxed.gpu.global.u32 [%0], 0;" :: "l"(cnt) : "memory");
            asm volatile("red.release.gpu.global.add.u32 [%0], 1;" :: "l"(gen_p) : "memory");
        } else {
            unsigned cur;
            do {
                asm volatile("ld.acquire.gpu.global.u32 %0, [%1];" : "=r"(cur) : "l"(gen_p) : "memory");
            } while (cur == gen);
        }
    }
    __syncthreads();
}
__device__ __forceinline__ void gbar() { gbar_n(&g_barcnt, &g_bargen, GB); }

__global__ void k_nop() {}

__global__ void __launch_bounds__(NT) k_setup(const float* __restrict__ F,
                                              const float* __restrict__ C,
                                              const float* __restrict__ c) {
    int idx = blockIdx.x * NT + threadIdx.x;
    if (idx < ND * NX) {
        int i = idx / NX, m = idx - i * NX;
        g_Ft[i * NX + m] = F[m * ND + i];
    }
    if (idx < NX * NX) {
        int i = idx >> 7, j = idx & 127;
        g_Vb[0][idx] = C[i * ND + j];
    }
    if (idx < NX) g_vb[0][idx] = c[idx];
    if (idx < TH) { g_delta[idx] = 0u; g_vmax[idx] = 0u; }
    if (idx == 0) g_niters = TH;
}

// ---------------- backward Riccati (persistent, 32 CTAs, 2 barriers/iter) ----------------
__global__ void __launch_bounds__(NT) k_backward(const float* __restrict__ F,
                                                 const float* __restrict__ f,
                                                 const float* __restrict__ C,
                                                 const float* __restrict__ c) {
    const int b = blockIdx.x, tid = threadIdx.x;
    const int jb = b * 4;          // owned K / V' / M columns
    const int c0 = b * 2;          // owned X' columns
    extern __shared__ float sm[];

    __shared__ __align__(16) float ft6[6][NX];
    __shared__ __align__(16) float fv6[6][NX];
    __shared__ __align__(16) float pf2[2 * 6 * NX];
    __shared__ __align__(16) float prAp[2][64];
    __shared__ __align__(16) float prIp[2][64];
    __shared__ __align__(16) float fshp[2][64];
    __shared__ float rmax[8], rvmx[8];
    __shared__ __align__(16) float Wsh[256];
    __shared__ __align__(16) float Zsh[256];
    __shared__ __align__(16) float ush[128];
    __shared__ __align__(16) float wqs[64];
    __shared__ __align__(16) float zqs[64];
    __shared__ __align__(16) float ksh[64];
    __shared__ __align__(16) float Ksh[256];     // [u*4 + jj]

    // stage F_u once into dynamic smem (pitch 64)
    for (int o = tid; o < 128 * 64; o += NT) {
        int i = o >> 6, u = o & 63;
        sm[OFF_FU + i * 64 + u] = F[i * ND + NX + u];
    }
    __syncthreads();

    for (int it = 0; it < TH; ++it) {
        const int p = it & 1;
        const bool newton = (it >= IT_SW);
        const float* V  = g_Vb[p];
        const float* v  = g_vb[p];
        float* Vn = g_Vb[p ^ 1];
        float* vn = g_vb[p ^ 1];
        const int i0 = b * RPB;

        // ===== phase 1: register-blocked Q build (one pass, 6 rows) =====
        for (int o = tid; o < 6 * NX; o += NT) {
            int r = o >> 7, k = o & 127;
            ft6[r][k] = g_Ft[(i0 + r) * NX + k];
        }
        __syncthreads();
        {
            const int m = tid & 127, g = tid >> 7;
            float a0 = 0.f, a1 = 0.f, a2 = 0.f, a3 = 0.f, a4 = 0.f, a5 = 0.f;
            const float* Vg = V + (g * 64) * NX + m;
            #pragma unroll
            for (int k = 0; k < 64; k += 4) {
                float v0 = __ldcg(Vg + (k    ) * NX);
                float v1 = __ldcg(Vg + (k + 1) * NX);
                float v2 = __ldcg(Vg + (k + 2) * NX);
                float v3 = __ldcg(Vg + (k + 3) * NX);
                #pragma unroll
                for (int r = 0; r < 6; ++r) {
                    float4 fr = *(const float4*)&ft6[r][g * 64 + k];
                    float t = fr.x * v0 + fr.y * v1 + fr.z * v2 + fr.w * v3;
                    if (r == 0) a0 += t; else if (r == 1) a1 += t;
                    else if (r == 2) a2 += t; else if (r == 3) a3 += t;
                    else if (r == 4) a4 += t; else a5 += t;
                }
            }
            pf2[g * 768 + 0 * 128 + m] = a0;
            pf2[g * 768 + 1 * 128 + m] = a1;
            pf2[g * 768 + 2 * 128 + m] = a2;
            pf2[g * 768 + 3 * 128 + m] = a3;
            pf2[g * 768 + 4 * 128 + m] = a4;
            pf2[g * 768 + 5 * 128 + m] = a5;
        }
        __syncthreads();
        {
            float* fv6f = &fv6[0][0];
            for (int o = tid; o < 768; o += NT) fv6f[o] = pf2[o] + pf2[768 + o];
        }
        __syncthreads();
        // q rows
        if (tid < 192) {
            int r = tid >> 5, lane = tid & 31;
            float s = 0.f;
            #pragma unroll
            for (int m = lane; m < 128; m += 32)
                s += fv6[r][m] * f[m] + ft6[r][m] * __ldcg(&v[m]);
            #pragma unroll
            for (int o = 16; o > 0; o >>= 1) s += __shfl_down_sync(0xffffffffu, s, o);
            if (lane == 0) g_q[i0 + r] = c[i0 + r] + s;
        }
        // Q rows (6-row register blocked over F reads)
        if (tid < ND) {
            const int j = tid;
            float acc[6];
            #pragma unroll
            for (int r = 0; r < 6; ++r) acc[r] = C[(i0 + r) * ND + j];
            #pragma unroll 8
            for (int mm = 0; mm < 128; mm += 4) {
                float s0 = F[(mm    ) * ND + j];
                float s1 = F[(mm + 1) * ND + j];
                float s2 = F[(mm + 2) * ND + j];
                float s3 = F[(mm + 3) * ND + j];
                #pragma unroll
                for (int r = 0; r < 6; ++r) {
                    float4 fr = *(const float4*)&fv6[r][mm];
                    acc[r] += fr.x * s0 + fr.y * s1 + fr.z * s2 + fr.w * s3;
                }
            }
            #pragma unroll
            for (int r = 0; r < 6; ++r) g_Q[(i0 + r) * ND + j] = acc[r];
        }
        gbar();   // barrier 1: Q ready

        // old V values for delta (f4, own 4 columns)
        float4 vold4;
        if (tid < 128) vold4 = __ldcg((const float4*)&V[tid * NX + jb]);

        // ===== bulk staging (high MLP): QXU always; QUU/X/XT for Newton =====
        #pragma unroll
        for (int o = tid; o < 2048; o += NT) {
            int row = o >> 4, c4 = o & 15;
            float4 q4v = __ldcg((const float4*)&g_Q[row * ND + NX + c4 * 4]);
            *(float4*)&sm[OFF_QXU + row * 64 + c4 * 4] = q4v;
        }
        {
            int jj = tid >> 6, m = tid & 63;
            sm[OFF_Y4 + jj * 64 + m] = __ldcg(&g_Q[(NX + m) * ND + jb + jj]);
        }
        if (b == 0 && tid < 64) sm[OFF_QU + tid] = __ldcg(&g_q[NX + tid]);
        if (newton) {
            #pragma unroll
            for (int o = tid; o < 1024; o += NT) {
                int row = o >> 4, c4 = o & 15;
                float4 q4v = __ldcg((const float4*)&g_Q[(NX + row) * ND + NX + c4 * 4]);
                *(float4*)&sm[OFF_QUU + row * 64 + c4 * 4] = q4v;
            }
            #pragma unroll
            for (int o = tid; o < 1024; o += NT) {
                float4 x4 = __ldcg((const float4*)&g_invb[p][o * 4]);
                *(float4*)&sm[OFF_X + o * 4] = x4;
            }
            #pragma unroll
            for (int o = tid; o < 1024; o += NT) {
                float4 x4 = __ldcg((const float4*)&g_invbT[p][o * 4]);
                *(float4*)&sm[OFF_XT + o * 4] = x4;
            }
        }

        // ===== produce X (row) + Xt (transposed) in smem (GJ path) =====
        if (!newton) {
            // register Gauss-Jordan, every CTA; ONE sync per pivot (parity buffers)
            const int r = tid >> 2, q4 = tid & 3;
            float ar[16], vi[16];
            #pragma unroll
            for (int jq = 0; jq < 4; ++jq) {
                float4 a4 = __ldcg((const float4*)&g_Q[(NX + r) * ND + NX + q4 * 16 + jq * 4]);
                ar[jq * 4 + 0] = a4.x; ar[jq * 4 + 1] = a4.y;
                ar[jq * 4 + 2] = a4.z; ar[jq * 4 + 3] = a4.w;
            }
            #pragma unroll
            for (int jj = 0; jj < 16; ++jj) vi[jj] = (q4 * 16 + jj == r) ? 1.0f : 0.0f;

            #pragma unroll 1
            for (int pv = 0; pv < 64; ++pv) {
                const int ps = pv >> 4, pj = pv & 15, par = pv & 1;
                float apj = ar[pj];
                float pivv = __shfl_sync(0xffffffffu, apj, (pv * 4 + ps) & 31);
                if (q4 == ps) fshp[par][r] = apj;
                if (r == pv) {
                    float rcp = 1.0f / pivv;
                    #pragma unroll
                    for (int jj = 0; jj < 16; ++jj) {
                        ar[jj] *= rcp; vi[jj] *= rcp;
                        prAp[par][q4 * 16 + jj] = ar[jj];
                        prIp[par][q4 * 16 + jj] = vi[jj];
                    }
                }
                __syncthreads();
                if (r != pv) {
                    const float fr = fshp[par][r];
                    #pragma unroll
                    for (int jj = 0; jj < 16; ++jj) {
                        ar[jj] = fmaf(-fr, prAp[par][q4 * 16 + jj], ar[jj]);
                        vi[jj] = fmaf(-fr, prIp[par][q4 * 16 + jj], vi[jj]);
                    }
                }
            }
            #pragma unroll
            for (int jj = 0; jj < 16; ++jj) {
                int col = q4 * 16 + jj;
                sm[OFF_X  + r * 64 + col] = vi[jj];
                sm[OFF_XT + col * 64 + r] = vi[jj];
                if (b == 0) {
                    g_invb[p ^ 1][r * 64 + col]  = vi[jj];
                    g_invbT[p ^ 1][col * 64 + r] = vi[jj];
                }
            }
        }
        __syncthreads();

        // ===== S1: W = X y ; b0: wq = X qu =====
        {
            int u = tid & 63, jj = tid >> 6;
            float s = 0.f;
            #pragma unroll 4
            for (int mq = 0; mq < 64; mq += 4) {
                float4 x4 = *(const float4*)&sm[OFF_X + u * 64 + mq];
                float4 y4 = *(const float4*)&sm[OFF_Y4 + jj * 64 + mq];
                s += x4.x * y4.x + x4.y * y4.y + x4.z * y4.z + x4.w * y4.w;
            }
            Wsh[jj * 64 + u] = s;
            if (b == 0 && tid < 64) {
                float t = 0.f;
                #pragma unroll 4
                for (int mq = 0; mq < 64; mq += 4) {
                    float4 x4 = *(const float4*)&sm[OFF_X + tid * 64 + mq];
                    float4 q4 = *(const float4*)&sm[OFF_QU + mq];
                    t += x4.x * q4.x + x4.y * q4.y + x4.z * q4.z + x4.w * q4.w;
                }
                wqs[tid] = t;
            }
        }
        __syncthreads();

        if (!newton) {
            // K = -W, k = -wq
            int u = tid & 63, jj = tid >> 6;
            float kv = -Wsh[jj * 64 + u];
            Ksh[u * 4 + jj] = kv;
            g_Ks[(size_t)it * (NU * NX) + u * NX + jb + jj] = kv;
            if (b == 0 && tid < 64) ksh[tid] = -wqs[tid];
        } else {
            // S2: Z = Quu W ; ush = Quu x_cc ; b0: zq = Quu wq
            {
                int r = tid & 63, jj = tid >> 6;
                float s = 0.f;
                #pragma unroll 4
                for (int mq = 0; mq < 64; mq += 4) {
                    float4 q4 = *(const float4*)&sm[OFF_QUU + r * 64 + mq];
                    float4 w4 = *(const float4*)&Wsh[jj * 64 + mq];
                    s += q4.x * w4.x + q4.y * w4.y + q4.z * w4.z + q4.w * w4.w;
                }
                Zsh[jj * 64 + r] = s;
                if (tid < 128) {
                    int rr = tid & 63, ci = tid >> 6, cc = c0 + ci;
                    float t = 0.f;
                    #pragma unroll 4
                    for (int mq = 0; mq < 64; mq += 4) {
                        float4 q4 = *(const float4*)&sm[OFF_QUU + rr * 64 + mq];
                        float4 x4 = *(const float4*)&sm[OFF_XT + cc * 64 + mq];
                        t += q4.x * x4.x + q4.y * x4.y + q4.z * x4.z + q4.w * x4.w;
                    }
                    ush[ci * 64 + rr] = t;
                }
                if (b == 0 && tid < 64) {
                    float t = 0.f;
                    #pragma unroll 4
                    for (int mq = 0; mq < 64; mq += 4) {
                        float4 q4 = *(const float4*)&sm[OFF_QUU + tid * 64 + mq];
                        float4 w4 = *(const float4*)&wqs[mq];
                        t += q4.x * w4.x + q4.y * w4.y + q4.z * w4.z + q4.w * w4.w;
                    }
                    zqs[tid] = t;
                }
            }
            __syncthreads();
            // S3: K = -(2W - X Z) ; X' = 2X - X ush ; b0: k
            {
                int u = tid & 63, jj = tid >> 6;
                float s = 0.f;
                #pragma unroll 4
                for (int mq = 0; mq < 64; mq += 4) {
                    float4 x4 = *(const float4*)&sm[OFF_X + u * 64 + mq];
                    float4 z4 = *(const float4*)&Zsh[jj * 64 + mq];
                    s += x4.x * z4.x + x4.y * z4.y + x4.z * z4.z + x4.w * z4.w;
                }
                float kv = -(2.0f * Wsh[jj * 64 + u] - s);
                Ksh[u * 4 + jj] = kv;
                g_Ks[(size_t)it * (NU * NX) + u * NX + jb + jj] = kv;
                if (tid < 128) {
                    int rr = tid & 63, ci = tid >> 6, cc = c0 + ci;
                    float t = 0.f;
                    #pragma unroll 4
                    for (int mq = 0; mq < 64; mq += 4) {
                        float4 x4 = *(const float4*)&sm[OFF_X + rr * 64 + mq];
                        float4 u4 = *(const float4*)&ush[ci * 64 + mq];
                        t += x4.x * u4.x + x4.y * u4.y + x4.z * u4.z + x4.w * u4.w;
                    }
                    float xn = 2.0f * sm[OFF_X + rr * 64 + cc] - t;
                    g_invb[p ^ 1][rr * 64 + cc]  = xn;
                    g_invbT[p ^ 1][cc * 64 + rr] = xn;
                }
                if (b == 0 && tid < 64) {
                    float t = 0.f;
                    #pragma unroll 4
                    for (int mq = 0; mq < 64; mq += 4) {
                        float4 x4 = *(const float4*)&sm[OFF_X + tid * 64 + mq];
                        float4 z4 = *(const float4*)&zqs[mq];
                        t += x4.x * z4.x + x4.y * z4.y + x4.z * z4.z + x4.w * z4.w;
                    }
                    ksh[tid] = -(2.0f * wqs[tid] - t);
                }
            }
        }
        __syncthreads();

        // ===== V' (t<128) and M (t>=128), 4 columns each; v', b; delta =====
        {
            float dmax = 0.f, vmx = 0.f;
            const int i = tid & 127;
            const bool doM = tid >= 128;
            const int base = (doM ? OFF_FU : OFF_QXU) + i * 64;
            float a0 = 0.f, a1 = 0.f, a2 = 0.f, a3 = 0.f;
            #pragma unroll 4
            for (int uq = 0; uq < 64; uq += 4) {
                float4 s4 = *(const float4*)&sm[base + uq];
                float4 k0 = *(const float4*)&Ksh[(uq    ) * 4];
                float4 k1 = *(const float4*)&Ksh[(uq + 1) * 4];
                float4 k2 = *(const float4*)&Ksh[(uq + 2) * 4];
                float4 k3 = *(const float4*)&Ksh[(uq + 3) * 4];
                a0 += s4.x * k0.x + s4.y * k1.x + s4.z * k2.x + s4.w * k3.x;
                a1 += s4.x * k0.y + s4.y * k1.y + s4.z * k2.y + s4.w * k3.y;
                a2 += s4.x * k0.z + s4.y * k1.z + s4.z * k2.z + s4.w * k3.z;
                a3 += s4.x * k0.w + s4.y * k1.w + s4.z * k2.w + s4.w * k3.w;
            }
            if (!doM) {
                float4 qx = __ldcg((const float4*)&g_Q[i * ND + jb]);
                float4 vnewv;
                vnewv.x = qx.x + a0; vnewv.y = qx.y + a1;
                vnewv.z = qx.z + a2; vnewv.w = qx.w + a3;
                *(float4*)&Vn[i * NX + jb] = vnewv;
                dmax = fmaxf(fmaxf(fabsf(vnewv.x - vold4.x), fabsf(vnewv.y - vold4.y)),
                             fmaxf(fabsf(vnewv.z - vold4.z), fabsf(vnewv.w - vold4.w)));
                vmx  = fmaxf(fmaxf(fabsf(vnewv.x), fabsf(vnewv.y)),
                             fmaxf(fabsf(vnewv.z), fabsf(vnewv.w)));
            } else {
                float4 fx;
                fx.x = F[i * ND + jb    ];
                fx.y = F[i * ND + jb + 1];
                fx.z = F[i * ND + jb + 2];
                fx.w = F[i * ND + jb + 3];
                float4 mv;
                mv.x = fx.x + a0; mv.y = fx.y + a1;
                mv.z = fx.z + a2; mv.w = fx.w + a3;
                *(float4*)&g_Ms[(size_t)it * (NX * NX) + i * NX + jb] = mv;
            }
            if (b == 0) {
                float s = 0.f, sb = 0.f;
                #pragma unroll 4
                for (int uq = 0; uq < 64; uq += 4) {
                    float4 k4 = *(const float4*)&ksh[uq];
                    float4 qx4 = *(const float4*)&sm[OFF_QXU + i * 64 + uq];
                    float4 fu4 = *(const float4*)&sm[OFF_FU + i * 64 + uq];
                    s  += qx4.x * k4.x + qx4.y * k4.y + qx4.z * k4.z + qx4.w * k4.w;
                    sb += fu4.x * k4.x + fu4.y * k4.y + fu4.z * k4.z + fu4.w * k4.w;
                }
                if (!doM) {
                    vn[i] = __ldcg(&g_q[i]) + s;
                    g_bs[it * NX + i] = f[i] + sb;
                    if (i < NU) g_ks[it * NU + i] = ksh[i];
                }
            }
            #pragma unroll
            for (int o = 16; o > 0; o >>= 1) {
                dmax = fmaxf(dmax, __shfl_down_sync(0xffffffffu, dmax, o));
                vmx  = fmaxf(vmx,  __shfl_down_sync(0xffffffffu, vmx, o));
            }
            if ((tid & 31) == 0) { rmax[tid >> 5] = dmax; rvmx[tid >> 5] = vmx; }
            __syncthreads();
            if (tid == 0) {
                float d = rmax[0], vv = rvmx[0];
                #pragma unroll
                for (int w = 1; w < 8; ++w) { d = fmaxf(d, rmax[w]); vv = fmaxf(vv, rvmx[w]); }
                atomicMax(&g_delta[it], __float_as_uint(d));
                atomicMax(&g_vmax[it], __float_as_uint(vv));
            }
        }
        gbar();   // barrier 2: end of iteration

        {
            float dd = __uint_as_float(__ldcg(&g_delta[it]));
            float vv = __uint_as_float(__ldcg(&g_vmax[it]));
            if (dd <= 2.5e-6f * vv) {
                if (b == 0 && tid == 0) g_niters = it + 1;
                break;
            }
        }
    }
}

// ---------------- persistent power kernel: copy + 5 affine squarings ----------------
__global__ void __launch_bounds__(256) k_power() {
    const int tid = threadIdx.x;
    {
        const int ni = g_niters;
        const float* src = g_Ms + (size_t)(ni - 1) * (NX * NX);
        for (int o = blockIdx.x * 256 + tid; o < NX * NX; o += PB * 256)
            g_P[0][o] = __ldcg(&src[o]);
        if (blockIdx.x == 16 && tid < NX) g_pb[0][tid] = __ldcg(&g_bs[(ni - 1) * NX + tid]);
    }
    gbar_n(&g_barcnt2, &g_bargen2, PB);

    __shared__ __align__(16) float As[32][33];
    __shared__ __align__(16) float Bs[32][33];
    #pragma unroll 1
    for (int s = 0; s < 5; ++s) {
        const int p = s & 1;
        const float* Ms = g_P[p];
        const float* bs = g_pb[p];
        float* Md = g_P[p ^ 1];
        float* bd = g_pb[p ^ 1];

        if (blockIdx.x == 16) {
            if (tid < NX) {
                float s0 = 0.f, s1 = 0.f;
                #pragma unroll 8
                for (int k = 0; k < NX; k += 2) {
                    s0 += __ldcg(&Ms[tid * NX + k    ]) * __ldcg(&bs[k    ]);
                    s1 += __ldcg(&Ms[tid * NX + k + 1]) * __ldcg(&bs[k + 1]);
                }
                bd[tid] = (s0 + s1) + __ldcg(&bs[tid]);
            }
        } else {
            const int tr = blockIdx.x >> 2, tc = blockIdx.x & 3;
            const int r  = tid >> 3;
            const int c4 = (tid & 7) * 4;
            float acc0 = 0.f, acc1 = 0.f, acc2 = 0.f, acc3 = 0.f;
            for (int kb = 0; kb < 4; ++kb) {
                #pragma unroll
                for (int l = tid; l < 1024; l += 256) {
                    int lr = l >> 5, lc = l & 31;
                    As[lr][lc] = __ldcg(&Ms[(tr * 32 + lr) * NX + kb * 32 + lc]);
                    Bs[lr][lc] = __ldcg(&Ms[(kb * 32 + lr) * NX + tc * 32 + lc]);
                }
                __syncthreads();
                #pragma unroll
                for (int k = 0; k < 32; ++k) {
                    float av = As[r][k];
                    acc0 += av * Bs[k][c4    ];
                    acc1 += av * Bs[k][c4 + 1];
                    acc2 += av * Bs[k][c4 + 2];
                    acc3 += av * Bs[k][c4 + 3];
                }
                __syncthreads();
            }
            float* dst = Md + (size_t)(tr * 32 + r) * NX + tc * 32 + c4;
            dst[0] = acc0; dst[1] = acc1; dst[2] = acc2; dst[3] = acc3;
        }
        gbar_n(&g_barcnt2, &g_bargen2, PB);
    }
}

// ---------------- segment heads (M^32 chain) + time-varying tail ----------------
__global__ void __launch_bounds__(256) k_heads(const float* __restrict__ x0,
                                               float* __restrict__ out_states) {
    const int tid = threadIdx.x;
    const int row = tid & 127, half = tid >> 7;
    const int ni = g_niters;
    const int tconv = TH - ni;
    const int NS = (tconv + 1) / SEG;
    __shared__ __align__(16) float xs[NX];
    __shared__ __align__(16) float ps[256];

    float mreg[64];
    {
        const float* Mc = g_P[1] + row * NX + half * 64;
        #pragma unroll
        for (int j = 0; j < 64; j += 4) {
            float4 t4 = *(const float4*)(Mc + j);
            mreg[j] = t4.x; mreg[j + 1] = t4.y; mreg[j + 2] = t4.z; mreg[j + 3] = t4.w;
        }
    }
    float breg = g_pb[1][row];

    if (tid < NX) { xs[tid] = x0[tid]; out_states[tid] = x0[tid]; }
    __syncthreads();

    for (int s = 1; s <= NS; ++s) {
        float a0 = 0.f, a1 = 0.f, a2 = 0.f, a3 = 0.f;
        #pragma unroll
        for (int j = 0; j < 64; j += 4) {
            a0 += mreg[j    ] * xs[half * 64 + j    ];
            a1 += mreg[j + 1] * xs[half * 64 + j + 1];
            a2 += mreg[j + 2] * xs[half * 64 + j + 2];
            a3 += mreg[j + 3] * xs[half * 64 + j + 3];
        }
        ps[tid] = (a0 + a1) + (a2 + a3);
        __syncthreads();
        if (half == 0) {
            float xn = ps[row] + ps[128 + row] + breg;
            xs[row] = xn;
            out_states[(size_t)s * SEG * NX + row] = xn;
        }
        __syncthreads();
    }

    {
        const float* Mc = g_Ms + (size_t)(ni - 1) * (NX * NX) + row * NX + half * 64;
        #pragma unroll
        for (int j = 0; j < 64; j += 4) {
            float4 t4 = *(const float4*)(Mc + j);
            mreg[j] = t4.x; mreg[j + 1] = t4.y; mreg[j + 2] = t4.z; mreg[j + 3] = t4.w;
        }
        breg = g_bs[(ni - 1) * NX + row];
    }
    for (int t = NS * SEG; t < TH; ++t) {
        if (t > tconv) {
            const int r = TH - 1 - t;
            const float* Mr = g_Ms + (size_t)r * (NX * NX) + row * NX + half * 64;
            #pragma unroll
            for (int j = 0; j < 64; j += 4) {
                float4 t4 = *(const float4*)(Mr + j);
                mreg[j] = t4.x; mreg[j + 1] = t4.y; mreg[j + 2] = t4.z; mreg[j + 3] = t4.w;
            }
            breg = g_bs[r * NX + row];
        }
        float a0 = 0.f, a1 = 0.f, a2 = 0.f, a3 = 0.f;
        #pragma unroll
        for (int j = 0; j < 64; j += 4) {
            a0 += mreg[j    ] * xs[half * 64 + j    ];
            a1 += mreg[j + 1] * xs[half * 64 + j + 1];
            a2 += mreg[j + 2] * xs[half * 64 + j + 2];
            a3 += mreg[j + 3] * xs[half * 64 + j + 3];
        }
        ps[tid] = (a0 + a1) + (a2 + a3);
        __syncthreads();
        if (half == 0) {
            float xn = ps[row] + ps[128 + row] + breg;
            xs[row] = xn;
            out_states[(size_t)(t + 1) * NX + row] = xn;
        }
        __syncthreads();
    }
}

// ---------------- parallel segment fill ----------------
__global__ void __launch_bounds__(256) k_fill(float* __restrict__ out_states) {
    const int s = blockIdx.x;
    const int tid = threadIdx.x;
    const int row = tid & 127, half = tid >> 7;
    const int ni = g_niters;
    const int tconv = TH - ni;
    const int NS = (tconv + 1) / SEG;
    if (s >= NS) return;
    __shared__ __align__(16) float xs[NX];
    __shared__ __align__(16) float ps[256];

    float mreg[64];
    {
        const float* Mc = g_Ms + (size_t)(ni - 1) * (NX * NX) + row * NX + half * 64;
        #pragma unroll
        for (int j = 0; j < 64; j += 4) {
            float4 t4 = *(const float4*)(Mc + j);
            mreg[j] = t4.x; mreg[j + 1] = t4.y; mreg[j + 2] = t4.z; mreg[j + 3] = t4.w;
        }
    }
    float breg = g_bs[(ni - 1) * NX + row];

    if (tid < NX) xs[tid] = out_states[(size_t)s * SEG * NX + tid];
    __syncthreads();

    #pragma unroll 1
    for (int j2 = 1; j2 < SEG; ++j2) {
        float a0 = 0.f, a1 = 0.f, a2 = 0.f, a3 = 0.f;
        #pragma unroll
        for (int j = 0; j < 64; j += 4) {
            a0 += mreg[j    ] * xs[half * 64 + j    ];
            a1 += mreg[j + 1] * xs[half * 64 + j + 1];
            a2 += mreg[j + 2] * xs[half * 64 + j + 2];
            a3 += mreg[j + 3] * xs[half * 64 + j + 3];
        }
        ps[tid] = (a0 + a1) + (a2 + a3);
        __syncthreads();
        if (half == 0) {
            float xn = ps[row] + ps[128 + row] + breg;
            xs[row] = xn;
            out_states[(size_t)(s * SEG + j2) * NX + row] = xn;
        }
        __syncthreads();
    }
}

// ---------------- epilogue: 4 timesteps per block ----------------
__global__ void __launch_bounds__(192) k_epilogue(const float* __restrict__ C,
                                                  const float* __restrict__ c,
                                                  const float* __restrict__ states,
                                                  float* __restrict__ us,
                                                  float* __restrict__ costs) {
    const int t0 = blockIdx.x * 4, tid = threadIdx.x;
    const int ni = g_niters;
    __shared__ __align__(16) float zs[4][ND];
    __shared__ __align__(16) float red[192];

    #pragma unroll
    for (int k = 0; k < 4; ++k) {
        int t = t0 + k;
        if (tid < NX) zs[k][tid] = (t <= TH) ? states[(size_t)t * NX + tid] : 0.0f;
        else zs[k][tid] = 0.0f;
    }
    __syncthreads();

    if (tid < NU) {
        #pragma unroll
        for (int k = 0; k < 4; ++k) {
            int t = t0 + k;
            if (t < TH) {
                int r = TH - 1 - t; if (r > ni - 1) r = ni - 1;
                const float* Kr = g_Ks + (size_t)r * (NU * NX) + tid * NX;
                float a0 = 0.f, a1 = 0.f, a2 = 0.f, a3 = 0.f;
                #pragma unroll 8
                for (int j = 0; j < NX; j += 4) {
                    a0 += Kr[j    ] * zs[k][j    ];
                    a1 += Kr[j + 1] * zs[k][j + 1];
                    a2 += Kr[j + 2] * zs[k][j + 2];
                    a3 += Kr[j + 3] * zs[k][j + 3];
                }
                float u = g_ks[r * NU + tid] + (a0 + a1) + (a2 + a3);
                zs[k][NX + tid] = u;
                us[(size_t)t * NU + tid] = u;
            }
        }
    }
    __syncthreads();

    float cz0 = 0.f, cz1 = 0.f, cz2 = 0.f, cz3 = 0.f;
    #pragma unroll 4
    for (int i = 0; i < ND; ++i) {
        float Cv = C[i * ND + tid];
        cz0 += zs[0][i] * Cv;
        cz1 += zs[1][i] * Cv;
        cz2 += zs[2][i] * Cv;
        cz3 += zs[3][i] * Cv;
    }
    const float cv = c[tid];
    float val[4];
    val[0] = zs[0][tid] * (0.5f * cz0 + cv);
    val[1] = zs[1][tid] * (0.5f * cz1 + cv);
    val[2] = zs[2][tid] * (0.5f * cz2 + cv);
    val[3] = zs[3][tid] * (0.5f * cz3 + cv);

    #pragma unroll
    for (int k = 0; k < 4; ++k) {
        __syncthreads();
        red[tid] = val[k];
        __syncthreads();
        #pragma unroll
        for (int s = 96; s >= 6; s >>= 1) {
            if (tid < s) red[tid] += red[tid + s];
            __syncthreads();
        }
        int t = t0 + k;
        if (tid == 0 && t <= TH)
            costs[t] = red[0] + red[1] + red[2] + red[3] + red[4] + red[5];
    }
}

// ---------------- launch ----------------
extern "C" void kernel_launch(void* const* d_in, const int* in_sizes, int n_in,
                              void* d_out, int out_size) {
    const float* F  = (const float*)d_in[0];
    const float* f  = (const float*)d_in[1];
    const float* C  = (const float*)d_in[2];
    const float* c  = (const float*)d_in[3];
    const float* x0 = (const float*)d_in[4];
    (void)in_sizes; (void)n_in; (void)out_size;

    float* out        = (float*)d_out;
    float* out_states = out;
    float* out_us     = out + (size_t)(TH + 1) * NX;
    float* out_costs  = out_us + (size_t)TH * NU;

    cudaFuncSetAttribute(k_backward, cudaFuncAttributeMaxDynamicSharedMemorySize, SMEM_BK);

    k_setup<<<96, NT>>>(F, C, c);         // user idx 0
    k_nop<<<1, 32>>>();                   // idx 1
    k_nop<<<1, 32>>>();                   // idx 2
    k_backward<<<GB, NT, SMEM_BK>>>(F, f, C, c);   // idx 3 -> ncu capture target
    k_power<<<PB, 256>>>();
    k_heads<<<1, 256>>>(x0, out_states);
    k_fill<<<64, 256>>>(out_states);
    k_epilogue<<<(TH + 4) / 4, 192>>>(C, c, out_states, out_us, out_costs);
}